// round 17
// baseline (speedup 1.0000x reference)
#include <cuda_runtime.h>
#include <cuda_bf16.h>
#include <cstdint>
#include <cstddef>

// B=4, C=128, N=64, HID=1536, PROJ=768
// feat fp32 [768][128]; hi/lo bf16 planes: f[768][128], w1t[1536][128],
// w2t[768][1536], h[768][1536]; partials fp32 [4][768][768].

__device__ float g_featf[768 * 128];
__device__ __align__(16) __nv_bfloat16 g_fh[768 * 128];
__device__ __align__(16) __nv_bfloat16 g_fl[768 * 128];
__device__ __align__(16) __nv_bfloat16 g_w1h[1536 * 128];
__device__ __align__(16) __nv_bfloat16 g_w1l[1536 * 128];
__device__ __align__(16) __nv_bfloat16 g_w2h[768 * 1536];
__device__ __align__(16) __nv_bfloat16 g_w2l[768 * 1536];
__device__ __align__(16) __nv_bfloat16 g_hh[768 * 1536];
__device__ __align__(16) __nv_bfloat16 g_hl[768 * 1536];
__device__ float g_part[4 * 768 * 768];

__device__ __forceinline__ void redadd(float* p, float v) {
    asm volatile("red.global.add.f32 [%0], %1;" :: "l"(p), "f"(v) : "memory");
}
__device__ __forceinline__ void cp_async16(uint32_t dst, const void* src) {
    asm volatile("cp.async.ca.shared.global [%0], [%1], 16;"
                 :: "r"(dst), "l"(src) : "memory");
}
__device__ __forceinline__ uint32_t bfpair(float x, float y) {
    __nv_bfloat162 p = __floats2bfloat162_rn(x, y);   // .x = low half = x
    return *reinterpret_cast<uint32_t*>(&p);
}
__device__ __forceinline__ float bflo(float v) {
    return v - __bfloat162float(__float2bfloat16(v));
}

// ---------------------------------------------------------------------------
__global__ void __launch_bounds__(256) init_featf() {
    const int i = blockIdx.x * 256 + threadIdx.x;   // 24576 f4
    reinterpret_cast<float4*>(g_featf)[i] = make_float4(0.f, 0.f, 0.f, 0.f);
}

// ---------------------------------------------------------------------------
// Reduce (R6/R12 proven): 4096 CTAs, out g_featf[m][c] fp32 (h/w via RED).
// ---------------------------------------------------------------------------
__global__ void __launch_bounds__(256, 4) reduce_kernel(const float* __restrict__ x) {
    __shared__ float dpart[8 * 64];
    __shared__ float ss_s[64];
    __shared__ float sa_s[64];
    const int tid = threadIdx.x;
    if (tid < 64) { ss_s[tid] = 0.f; sa_s[tid] = 0.f; }
    __syncthreads();

    const int slab = blockIdx.x >> 3;
    const int p    = blockIdx.x & 7;
    const int warp = tid >> 5;
    const int lane = tid & 31;
    const int q    = warp & 3;
    const int half = warp >> 2;
    const int j    = lane & 15;
    const int u    = lane >> 4;

    const float4* base = reinterpret_cast<const float4*>(x) + (size_t)slab * 65536
                         + (size_t)(8 * p) * 1024 + (16 * q + u) * 16 + j;

    float hreg[8];
#pragma unroll
    for (int i = 0; i < 8; ++i) hreg[i] = 0.f;
    float w0 = 0.f, w1 = 0.f, w2 = 0.f, w3 = 0.f;

#pragma unroll
    for (int dd = 0; dd < 4; ++dd) {
        const int dl = 2 * dd + half;
        const float4* pp = base + dl * 1024;
        float dacc = 0.f;
#pragma unroll
        for (int i = 0; i < 8; ++i) {
            float4 v = __ldcs(pp + i * 32);
            float s0 = v.x * v.x, s1 = v.y * v.y, s2 = v.z * v.z, s3 = v.w * v.w;
            w0 += s0; w1 += s1; w2 += s2; w3 += s3;
            float sm = (s0 + s1) + (s2 + s3);
            hreg[i] += sm;
            dacc    += sm;
        }
        dacc += __shfl_xor_sync(0xffffffffu, dacc, 16);
        if (lane < 16) dpart[dl * 64 + q * 16 + j] = dacc;
    }

#pragma unroll
    for (int i = 0; i < 8; ++i) {
        float v = hreg[i];
        v += __shfl_xor_sync(0xffffffffu, v, 1);
        v += __shfl_xor_sync(0xffffffffu, v, 2);
        v += __shfl_xor_sync(0xffffffffu, v, 4);
        v += __shfl_xor_sync(0xffffffffu, v, 8);
        if (j == 0) atomicAdd(&ss_s[16 * q + u + 2 * i], v);
    }

    atomicAdd(&sa_s[4 * j + 0], w0);
    atomicAdd(&sa_s[4 * j + 1], w1);
    atomicAdd(&sa_s[4 * j + 2], w2);
    atomicAdd(&sa_s[4 * j + 3], w3);

    __syncthreads();

    const int b = slab >> 7;
    const int c = slab & 127;
    if (tid < 32) {
        const int dl = tid >> 2;
        const int qq = tid & 3;
        const float4* dp = reinterpret_cast<const float4*>(&dpart[dl * 64 + qq * 16]);
        float s = 0.f;
#pragma unroll
        for (int k = 0; k < 4; ++k) {
            float4 v = dp[k];
            s += (v.x + v.y) + (v.z + v.w);
        }
        s += __shfl_xor_sync(0xffffffffu, s, 1);
        s += __shfl_xor_sync(0xffffffffu, s, 2);
        if (qq == 0)
            g_featf[(size_t)(b * 192 + 8 * p + dl) * 128 + c] = s * (1.0f / 4096.0f);
    }
    if (tid < 64) {
        redadd(&g_featf[(size_t)(b * 192 + 64 + tid) * 128 + c],
               ss_s[tid] * (1.0f / 4096.0f));
    } else if (tid < 128) {
        redadd(&g_featf[(size_t)(b * 192 + 128 + (tid - 64)) * 128 + c],
               sa_s[tid - 64] * (1.0f / 4096.0f));
    }
}

// ---------------------------------------------------------------------------
// feat fp32 -> bf16 hi/lo planes (same [m][c] layout). 24576 f4 elements.
// ---------------------------------------------------------------------------
__global__ void __launch_bounds__(256) split_feat_kernel() {
    const int i = blockIdx.x * 256 + threadIdx.x;
    float4 v = reinterpret_cast<const float4*>(g_featf)[i];
    uint2 hw, lw;
    hw.x = bfpair(v.x, v.y);
    hw.y = bfpair(v.z, v.w);
    lw.x = bfpair(bflo(v.x), bflo(v.y));
    lw.y = bfpair(bflo(v.z), bflo(v.w));
    reinterpret_cast<uint2*>(g_fh)[i] = hw;
    reinterpret_cast<uint2*>(g_fl)[i] = lw;
}

// ---------------------------------------------------------------------------
// Transpose + split: fp32 src [K][Nn] -> bf16 hi/lo [Nn][K].
// ---------------------------------------------------------------------------
__global__ void __launch_bounds__(256) transpose_split(const float* __restrict__ src,
                                                       int K, int Nn,
                                                       __nv_bfloat16* __restrict__ dhi,
                                                       __nv_bfloat16* __restrict__ dlo) {
    __shared__ float t[32][33];
    const int tx = threadIdx.x & 31;
    const int ty = threadIdx.x >> 5;   // 0..7
    const int n0 = blockIdx.x * 32;
    const int k0 = blockIdx.y * 32;
#pragma unroll
    for (int i = 0; i < 4; ++i)
        t[ty + 8 * i][tx] = src[(size_t)(k0 + ty + 8 * i) * Nn + n0 + tx];
    __syncthreads();
#pragma unroll
    for (int i = 0; i < 4; ++i) {
        float v = t[tx][ty + 8 * i];
        const size_t o = (size_t)(n0 + ty + 8 * i) * K + k0 + tx;
        __nv_bfloat16 h = __float2bfloat16(v);
        dhi[o] = h;
        dlo[o] = __float2bfloat16(v - __bfloat162float(h));
    }
}

// ---------------------------------------------------------------------------
// bf16-split GEMM via mma.sync.m16n8k16 (HMMA path, verified R16).
// D = Ah*Bh + Al*Bh + Ah*Bl (fp32 accum). Layouts / fragment maps as R16.
// ---------------------------------------------------------------------------
#define LDMX4(r, addr) \
    asm volatile("ldmatrix.sync.aligned.m8n8.x4.shared.b16 {%0,%1,%2,%3}, [%4];" \
                 : "=r"((r)[0]), "=r"((r)[1]), "=r"((r)[2]), "=r"((r)[3]) \
                 : "r"(addr))

__device__ __forceinline__ void mma_bf16(float* d, const uint32_t* a, const uint32_t* b) {
    asm volatile(
        "mma.sync.aligned.m16n8k16.row.col.f32.bf16.bf16.f32 "
        "{%0,%1,%2,%3}, {%4,%5,%6,%7}, {%8,%9}, {%0,%1,%2,%3};"
        : "+f"(d[0]), "+f"(d[1]), "+f"(d[2]), "+f"(d[3])
        : "r"(a[0]), "r"(a[1]), "r"(a[2]), "r"(a[3]), "r"(b[0]), "r"(b[1]));
}

template <int WM, bool TOUT>
__global__ void __launch_bounds__(256) gemm_mma(
    const __nv_bfloat16* __restrict__ Ah, const __nv_bfloat16* __restrict__ Al,
    const __nv_bfloat16* __restrict__ Bh, const __nv_bfloat16* __restrict__ Bl,
    const float* __restrict__ bias,
    __nv_bfloat16* __restrict__ OutHi, __nv_bfloat16* __restrict__ OutLo,
    float* __restrict__ OutF,
    int K, int Nn, int Kc) {
    constexpr int MT = 4;
    constexpr int NT = 2 * WM;
    constexpr int NWARPN = 8 / WM;
    constexpr int AROWS = 64 * WM;
    constexpr unsigned ROWB = 80;               // 64B data + 16B pad
    constexpr unsigned APLANE = AROWS * ROWB;
    constexpr unsigned BPLANE = 128 * ROWB;
    constexpr unsigned STG = 2 * APLANE + 2 * BPLANE;

    extern __shared__ char smem[];
    const unsigned sb = (unsigned)__cvta_generic_to_shared(smem);

    const int tid = threadIdx.x;
    const int lane = tid & 31;
    const int w = tid >> 5;
    const int wm = w / NWARPN;
    const int wn = w % NWARPN;
    const int m0 = blockIdx.y * AROWS;
    const int n0 = blockIdx.x * 128;
    const int kstart = blockIdx.z * Kc;
    const int T = Kc >> 5;

    float d[MT][NT][4];
#pragma unroll
    for (int mt = 0; mt < MT; ++mt)
#pragma unroll
        for (int nt = 0; nt < NT; ++nt)
#pragma unroll
            for (int e = 0; e < 4; ++e) d[mt][nt][e] = 0.f;

    const unsigned a_off = (unsigned)((wm * 64 + (lane & 15)) * ROWB
                                      + ((lane >> 4) & 1) * 16);
    const unsigned b_off = (unsigned)(2 * APLANE
                                      + (wn * 16 * WM + ((lane >> 4) & 1) * 8 + (lane & 7)) * ROWB
                                      + ((lane >> 3) & 1) * 16);

#define FILL(stg_, kc_)                                                        \
    do {                                                                       \
        _Pragma("unroll")                                                      \
        for (int i = 0; i < WM; ++i) {                                         \
            const int idx = tid + 256 * i;                                     \
            const int r = idx >> 2, cc = idx & 3;                              \
            const unsigned doff = (unsigned)((stg_) * STG + r * ROWB + cc * 16);\
            const size_t soff = (size_t)(m0 + r) * K + (kc_) + cc * 8;         \
            cp_async16(sb + doff, Ah + soff);                                  \
            cp_async16(sb + doff + APLANE, Al + soff);                         \
        }                                                                      \
        _Pragma("unroll")                                                      \
        for (int i = 0; i < 2; ++i) {                                          \
            const int idx = tid + 256 * i;                                     \
            const int r = idx >> 2, cc = idx & 3;                              \
            const unsigned doff = (unsigned)((stg_) * STG + 2 * APLANE         \
                                             + r * ROWB + cc * 16);            \
            const size_t soff = (size_t)(n0 + r) * K + (kc_) + cc * 8;         \
            cp_async16(sb + doff, Bh + soff);                                  \
            cp_async16(sb + doff + BPLANE, Bl + soff);                         \
        }                                                                      \
        asm volatile("cp.async.commit_group;" ::: "memory");                   \
    } while (0)

    FILL(0, kstart);
    asm volatile("cp.async.wait_group 0;" ::: "memory");
    __syncthreads();

    for (int t = 0; ; ) {
        const int st = t & 1;
        const bool more = (t + 1 < T);
        if (more) FILL(st ^ 1, kstart + 32 * (t + 1));

        const unsigned abase = sb + (unsigned)st * STG + a_off;
        const unsigned bbase = sb + (unsigned)st * STG + b_off;
#pragma unroll
        for (int ks = 0; ks < 2; ++ks) {
            uint32_t ah[MT][4], al[MT][4], bh[NT][2], bl[NT][2];
#pragma unroll
            for (int mt = 0; mt < MT; ++mt) {
                LDMX4(ah[mt], abase + (unsigned)(mt * 16 * ROWB + ks * 32));
                LDMX4(al[mt], abase + (unsigned)(APLANE + mt * 16 * ROWB + ks * 32));
            }
#pragma unroll
            for (int gi = 0; gi < NT / 2; ++gi) {
                uint32_t r[4];
                LDMX4(r, bbase + (unsigned)(gi * 16 * ROWB + ks * 32));
                bh[2 * gi][0] = r[0]; bh[2 * gi][1] = r[1];
                bh[2 * gi + 1][0] = r[2]; bh[2 * gi + 1][1] = r[3];
                LDMX4(r, bbase + (unsigned)(BPLANE + gi * 16 * ROWB + ks * 32));
                bl[2 * gi][0] = r[0]; bl[2 * gi][1] = r[1];
                bl[2 * gi + 1][0] = r[2]; bl[2 * gi + 1][1] = r[3];
            }
#pragma unroll
            for (int mt = 0; mt < MT; ++mt) {
#pragma unroll
                for (int nt = 0; nt < NT; ++nt) {
                    mma_bf16(d[mt][nt], ah[mt], bh[nt]);
                    mma_bf16(d[mt][nt], al[mt], bh[nt]);
                    mma_bf16(d[mt][nt], ah[mt], bl[nt]);
                }
            }
        }

        if (!more) break;
        asm volatile("cp.async.wait_group 0;" ::: "memory");
        __syncthreads();
        ++t;
    }
#undef FILL

    const int g = lane >> 2;
    const int tq = lane & 3;
    if (TOUT) {
#pragma unroll
        for (int nt = 0; nt < NT; ++nt) {
            const int nb = n0 + wn * 16 * WM + nt * 8 + 2 * tq;
            const float b0 = bias[nb];
            const float b1 = bias[nb + 1];
#pragma unroll
            for (int mt = 0; mt < MT; ++mt) {
                const int mr = m0 + wm * 64 + mt * 16 + g;
                float v0 = fmaxf(d[mt][nt][0] + b0, 0.f);
                float v1 = fmaxf(d[mt][nt][1] + b1, 0.f);
                float v2 = fmaxf(d[mt][nt][2] + b0, 0.f);
                float v3 = fmaxf(d[mt][nt][3] + b1, 0.f);
                *reinterpret_cast<uint32_t*>(&OutHi[(size_t)mr * Nn + nb]) = bfpair(v0, v1);
                *reinterpret_cast<uint32_t*>(&OutLo[(size_t)mr * Nn + nb]) =
                    bfpair(bflo(v0), bflo(v1));
                *reinterpret_cast<uint32_t*>(&OutHi[(size_t)(mr + 8) * Nn + nb]) = bfpair(v2, v3);
                *reinterpret_cast<uint32_t*>(&OutLo[(size_t)(mr + 8) * Nn + nb]) =
                    bfpair(bflo(v2), bflo(v3));
            }
        }
    } else {
        float* Co = OutF + (size_t)blockIdx.z * 768 * 768;
#pragma unroll
        for (int nt = 0; nt < NT; ++nt) {
            const int nb = n0 + wn * 16 * WM + nt * 8 + 2 * tq;
#pragma unroll
            for (int mt = 0; mt < MT; ++mt) {
                const int mr = m0 + wm * 64 + mt * 16 + g;
                *reinterpret_cast<float2*>(&Co[(size_t)mr * Nn + nb]) =
                    make_float2(d[mt][nt][0], d[mt][nt][1]);
                *reinterpret_cast<float2*>(&Co[(size_t)(mr + 8) * Nn + nb]) =
                    make_float2(d[mt][nt][2], d[mt][nt][3]);
            }
        }
    }
}

// ---------------------------------------------------------------------------
// Combine split-K=4 partials + bias.
// ---------------------------------------------------------------------------
__global__ void __launch_bounds__(256) combine_kernel(const float* __restrict__ part,
                                                      const float* __restrict__ bias,
                                                      float* __restrict__ out) {
    const float4* p = reinterpret_cast<const float4*>(part);
#pragma unroll
    for (int rep = 0; rep < 2; ++rep) {
        const int i = blockIdx.x * 512 + rep * 256 + threadIdx.x;
        float4 a = p[i];
        float4 b = p[i + 147456];
        float4 cc = p[i + 2 * 147456];
        float4 dd = p[i + 3 * 147456];
        float4 bb = reinterpret_cast<const float4*>(bias)[i % 192];
        float4 r;
        r.x = ((a.x + b.x) + (cc.x + dd.x)) + bb.x;
        r.y = ((a.y + b.y) + (cc.y + dd.y)) + bb.y;
        r.z = ((a.z + b.z) + (cc.z + dd.z)) + bb.z;
        r.w = ((a.w + b.w) + (cc.w + dd.w)) + bb.w;
        reinterpret_cast<float4*>(out)[i] = r;
    }
}

// ---------------------------------------------------------------------------
extern "C" void kernel_launch(void* const* d_in, const int* in_sizes, int n_in,
                              void* d_out, int out_size) {
    const float* x  = (const float*)d_in[0];
    const float* W1 = (const float*)d_in[1];
    const float* b1 = (const float*)d_in[2];
    const float* W2 = (const float*)d_in[3];
    const float* b2 = (const float*)d_in[4];
    float* out = (float*)d_out;

    __nv_bfloat16 *fh, *fl, *w1h, *w1l, *w2h, *w2l, *hh, *hl;
    float* part;
    cudaGetSymbolAddress((void**)&fh,  g_fh);
    cudaGetSymbolAddress((void**)&fl,  g_fl);
    cudaGetSymbolAddress((void**)&w1h, g_w1h);
    cudaGetSymbolAddress((void**)&w1l, g_w1l);
    cudaGetSymbolAddress((void**)&w2h, g_w2h);
    cudaGetSymbolAddress((void**)&w2l, g_w2l);
    cudaGetSymbolAddress((void**)&hh,  g_hh);
    cudaGetSymbolAddress((void**)&hl,  g_hl);
    cudaGetSymbolAddress((void**)&part, g_part);

    static bool attr_set = false;
    if (!attr_set) {
        cudaFuncSetAttribute(gemm_mma<1, true>,
                             cudaFuncAttributeMaxDynamicSharedMemorySize, 61440);
        cudaFuncSetAttribute(gemm_mma<2, false>,
                             cudaFuncAttributeMaxDynamicSharedMemorySize, 81920);
        attr_set = true;
    }

    // 0) zero fp32 feat (RED target)
    init_featf<<<96, 256>>>();

    // 1) weight prep
    transpose_split<<<dim3(48, 4), 256>>>(W1, 128, 1536, w1h, w1l);
    transpose_split<<<dim3(24, 48), 256>>>(W2, 1536, 768, w2h, w2l);

    // 2) streaming reduction -> g_featf [768][128]
    reduce_kernel<<<4096, 256>>>(x);

    // 3) feat -> bf16 hi/lo
    split_feat_kernel<<<96, 256>>>();

    // 4) h = relu(feat @ W1 + b1) -> hh/hl bf16 [768][1536]
    gemm_mma<1, true><<<dim3(12, 12, 1), 256, 61440>>>(
        fh, fl, w1h, w1l, b1, hh, hl, nullptr, 128, 1536, 128);

    // 5) partials = h @ W2 (split-K=4, ONE wave at 1 CTA/SM): grid (6,6,4)
    gemm_mma<2, false><<<dim3(6, 6, 4), 256, 81920>>>(
        hh, hl, w2h, w2l, nullptr, nullptr, nullptr, part, 1536, 768, 384);

    // 6) out = sum(4 partials) + b2
    combine_kernel<<<288, 256>>>(part, b2, out);
}